// round 3
// baseline (speedup 1.0000x reference)
#include <cuda_runtime.h>
#include <math.h>

#define NN 100000
#define EE 1600000
#define FNODE 79
#define FEDGE 10

// ---------------- scratch (device globals; no allocation) ----------------
__device__ float g_xl[NN * 128];
__device__ float g_xr[NN * 128];
__device__ float g_h[NN * 64];
__device__ int   g_deg[NN];
__device__ int   g_part[NN];
__device__ int   g_bsum[512];
__device__ int   g_off[NN + 1];
__device__ int   g_pos[NN];
__device__ int   g_perm[EE];
__device__ int   g_psrc[EE];
__device__ float g_pea[EE * FEDGE];

// ================= CSR build =================
__global__ void zero_deg_kernel(int* deg) {
    int i = blockIdx.x * blockDim.x + threadIdx.x;
    if (i < NN) deg[i] = 0;
}

__global__ void count_kernel(const int* __restrict__ dst, int* __restrict__ deg) {
    int e = blockIdx.x * blockDim.x + threadIdx.x;
    if (e < EE) atomicAdd(&deg[dst[e]], 1);
}

#define SCAN_B 256
__global__ void scan1_kernel(const int* __restrict__ deg, int* __restrict__ part,
                             int* __restrict__ bsum) {
    __shared__ int s[SCAN_B];
    int i = blockIdx.x * SCAN_B + threadIdx.x;
    int v = (i < NN) ? deg[i] : 0;
    s[threadIdx.x] = v;
    __syncthreads();
    for (int o = 1; o < SCAN_B; o <<= 1) {
        int t = (threadIdx.x >= o) ? s[threadIdx.x - o] : 0;
        __syncthreads();
        s[threadIdx.x] += t;
        __syncthreads();
    }
    if (i < NN) part[i] = s[threadIdx.x] - v;  // exclusive
    if (threadIdx.x == SCAN_B - 1) bsum[blockIdx.x] = s[threadIdx.x];
}

__global__ void scan2_kernel(int* __restrict__ bsum, int nb) {
    __shared__ int s[512];
    int t = threadIdx.x;
    int v = (t < nb) ? bsum[t] : 0;
    s[t] = v;
    __syncthreads();
    for (int o = 1; o < 512; o <<= 1) {
        int u = (t >= o) ? s[t - o] : 0;
        __syncthreads();
        s[t] += u;
        __syncthreads();
    }
    if (t < nb) bsum[t] = s[t] - v;  // exclusive
}

__global__ void scan3_kernel(const int* __restrict__ part, const int* __restrict__ bsum,
                             int* __restrict__ off, int* __restrict__ pos) {
    int i = blockIdx.x * blockDim.x + threadIdx.x;
    if (i < NN) {
        int o = part[i] + bsum[i / SCAN_B];
        off[i] = o;
        pos[i] = o;
    }
    if (i == 0) off[NN] = EE;
}

__global__ void scatter_kernel(const int* __restrict__ dst, int* __restrict__ pos,
                               int* __restrict__ perm) {
    int e = blockIdx.x * blockDim.x + threadIdx.x;
    if (e < EE) {
        int p = atomicAdd(&pos[dst[e]], 1);
        perm[p] = e;
    }
}

// permute src + edge_attr into CSR order (one-time; coalesced writes)
__global__ void gather_edges_kernel(const int* __restrict__ perm, const int* __restrict__ src,
                                    const float* __restrict__ ea,
                                    int* __restrict__ psrc, float* __restrict__ pea) {
    int j = blockIdx.x * blockDim.x + threadIdx.x;
    if (j >= EE) return;
    int e = perm[j];
    psrc[j] = src[e];
    const float* p = &ea[(size_t)e * FEDGE];
#pragma unroll
    for (int k = 0; k < FEDGE; k++) pea[(size_t)j * FEDGE + k] = p[k];
}

// ================= node transforms: xl = act(in)@Wl + bl ; xr likewise =================
#define TN 32
__global__ void transform_kernel(const float* __restrict__ in, int in_dim, int act,
                                 const float* __restrict__ Wl, const float* __restrict__ bl,
                                 const float* __restrict__ Wr, const float* __restrict__ br,
                                 int out_dim,
                                 float* __restrict__ xl, float* __restrict__ xr) {
    __shared__ float s_in[TN][FNODE + 1];
    int node0 = blockIdx.x * TN;
    int t = threadIdx.x;  // one output column per thread (blockDim.x == out_dim)

    int tot = TN * in_dim;
    for (int idx = t; idx < tot; idx += blockDim.x) {
        int n = idx / in_dim;
        int k = idx - n * in_dim;
        int g = node0 + n;
        float v = (g < NN) ? in[(size_t)g * in_dim + k] : 0.f;
        if (act) v = (v > 0.f) ? v : 0.01f * v;
        s_in[n][k] = v;
    }
    __syncthreads();

    float accl[TN], accr[TN];
    float blv = bl[t], brv = br[t];
#pragma unroll
    for (int n = 0; n < TN; n++) { accl[n] = blv; accr[n] = brv; }

    for (int k = 0; k < in_dim; k++) {
        float wl = Wl[k * out_dim + t];
        float wr = Wr[k * out_dim + t];
#pragma unroll
        for (int n = 0; n < TN; n++) {
            float v = s_in[n][k];
            accl[n] = fmaf(v, wl, accl[n]);
            accr[n] = fmaf(v, wr, accr[n]);
        }
    }
#pragma unroll
    for (int n = 0; n < TN; n++) {
        int g = node0 + n;
        if (g < NN) {
            xl[(size_t)g * out_dim + t] = accl[n];
            xr[(size_t)g * out_dim + t] = accr[n];
        }
    }
}

// ================= fused per-(node,head) GATv2: logits + online softmax + aggregation =================
// one warp per (destination node, head); CSR edge list (pre-permuted src / edge_attr)
// HC = total width, C = per-head width. 8 warps/block = 4 nodes/block.
template <int HC, int C, bool CONCAT>
__global__ void gat_node_kernel(const float* __restrict__ xl, const float* __restrict__ xr,
                                const int* __restrict__ psrc, const int* __restrict__ off,
                                const float* __restrict__ pea,
                                const float* __restrict__ We, const float* __restrict__ att,
                                const float* __restrict__ bias, float* __restrict__ out) {
    constexpr int R = C / 32;
    __shared__ float sWe[FEDGE * HC];
    __shared__ float sComb[8][C];

    int t = threadIdx.x;
    for (int i = t; i < FEDGE * HC; i += blockDim.x) sWe[i] = We[i];
    __syncthreads();

    int wid = t >> 5;
    int lane = t & 31;
    int gw = blockIdx.x * 8 + wid;
    int n = gw >> 1;
    int h = gw & 1;
    bool valid = (n < NN);

    float m = -INFINITY, dd = 0.f;
    float acc[R], xrv[R], attv[R];
#pragma unroll
    for (int r = 0; r < R; r++) acc[r] = 0.f;

    if (valid) {
#pragma unroll
        for (int r = 0; r < R; r++) {
            int c = h * C + lane + 32 * r;
            xrv[r] = xr[(size_t)n * HC + c];
            attv[r] = att[c];
        }

        int j0 = off[n], j1 = off[n + 1];
        int j = j0;
        // ---- 2-edge unrolled main loop ----
        for (; j + 1 < j1; j += 2) {
            int s0 = psrc[j], s1 = psrc[j + 1];
            float a0[FEDGE], a1[FEDGE];
#pragma unroll
            for (int k = 0; k < FEDGE; k++) {
                a0[k] = pea[(size_t)j * FEDGE + k];          // uniform-address broadcast
                a1[k] = pea[(size_t)(j + 1) * FEDGE + k];
            }
            float xlv0[R], xlv1[R];
#pragma unroll
            for (int r = 0; r < R; r++) {
                int c = h * C + lane + 32 * r;
                xlv0[r] = xl[(size_t)s0 * HC + c];
                xlv1[r] = xl[(size_t)s1 * HC + c];
            }
            float p0 = 0.f, p1 = 0.f;
#pragma unroll
            for (int r = 0; r < R; r++) {
                int c = h * C + lane + 32 * r;
                float ef0 = 0.f, ef1 = 0.f;
#pragma unroll
                for (int k = 0; k < FEDGE; k++) {
                    float w = sWe[k * HC + c];
                    ef0 = fmaf(a0[k], w, ef0);
                    ef1 = fmaf(a1[k], w, ef1);
                }
                float mm0 = xlv0[r] + xrv[r] + ef0;
                float mm1 = xlv1[r] + xrv[r] + ef1;
                mm0 = (mm0 > 0.f) ? mm0 : 0.2f * mm0;
                mm1 = (mm1 > 0.f) ? mm1 : 0.2f * mm1;
                p0 = fmaf(mm0, attv[r], p0);
                p1 = fmaf(mm1, attv[r], p1);
            }
#pragma unroll
            for (int o = 16; o > 0; o >>= 1) {
                p0 += __shfl_xor_sync(0xffffffffu, p0, o);
                p1 += __shfl_xor_sync(0xffffffffu, p1, o);
            }
            // batched online softmax update
            float nm = fmaxf(m, fmaxf(p0, p1));
            float cs = __expf(m - nm);
            float w0 = __expf(p0 - nm);
            float w1 = __expf(p1 - nm);
            dd = dd * cs + w0 + w1;
            m = nm;
#pragma unroll
            for (int r = 0; r < R; r++)
                acc[r] = fmaf(acc[r], cs, fmaf(w0, xlv0[r], w1 * xlv1[r]));
        }
        // ---- tail edge ----
        if (j < j1) {
            int s0 = psrc[j];
            float a0[FEDGE];
#pragma unroll
            for (int k = 0; k < FEDGE; k++) a0[k] = pea[(size_t)j * FEDGE + k];
            float xlv0[R];
#pragma unroll
            for (int r = 0; r < R; r++)
                xlv0[r] = xl[(size_t)s0 * HC + h * C + lane + 32 * r];
            float p0 = 0.f;
#pragma unroll
            for (int r = 0; r < R; r++) {
                int c = h * C + lane + 32 * r;
                float ef0 = 0.f;
#pragma unroll
                for (int k = 0; k < FEDGE; k++) ef0 = fmaf(a0[k], sWe[k * HC + c], ef0);
                float mm0 = xlv0[r] + xrv[r] + ef0;
                mm0 = (mm0 > 0.f) ? mm0 : 0.2f * mm0;
                p0 = fmaf(mm0, attv[r], p0);
            }
#pragma unroll
            for (int o = 16; o > 0; o >>= 1)
                p0 += __shfl_xor_sync(0xffffffffu, p0, o);
            float nm = fmaxf(m, p0);
            float cs = __expf(m - nm);
            float w0 = __expf(p0 - nm);
            dd = dd * cs + w0;
            m = nm;
#pragma unroll
            for (int r = 0; r < R; r++) acc[r] = fmaf(acc[r], cs, w0 * xlv0[r]);
        }
    }

    float inv = 1.f / fmaxf(dd, 1e-16f);

    if (CONCAT) {
        if (valid) {
#pragma unroll
            for (int r = 0; r < R; r++) {
                int c = h * C + lane + 32 * r;
                out[(size_t)n * HC + c] = acc[r] * inv + bias[c];
            }
        }
    } else {
        // mean over heads: combine the two head-warps of each node via smem
#pragma unroll
        for (int r = 0; r < R; r++) sComb[wid][lane + 32 * r] = acc[r] * inv;
        __syncthreads();
        if (valid && h == 0) {
#pragma unroll
            for (int r = 0; r < R; r++) {
                int c = lane + 32 * r;
                out[(size_t)n * C + c] =
                    0.5f * (sComb[wid][c] + sComb[wid + 1][c]) + bias[c];
            }
        }
    }
}

// ================= launch =================
extern "C" void kernel_launch(void* const* d_in, const int* in_sizes, int n_in,
                              void* d_out, int out_size) {
    const float* x    = (const float*)d_in[0];
    const int*   ei   = (const int*)d_in[1];
    const float* ea   = (const float*)d_in[2];
    const float* Wl0  = (const float*)d_in[3];
    const float* bl0  = (const float*)d_in[4];
    const float* Wr0  = (const float*)d_in[5];
    const float* br0  = (const float*)d_in[6];
    const float* We0  = (const float*)d_in[7];
    const float* att0 = (const float*)d_in[8];
    const float* bias0= (const float*)d_in[9];
    const float* Wl1  = (const float*)d_in[10];
    const float* bl1  = (const float*)d_in[11];
    const float* Wr1  = (const float*)d_in[12];
    const float* br1  = (const float*)d_in[13];
    const float* We1  = (const float*)d_in[14];
    const float* att1 = (const float*)d_in[15];
    const float* bias1= (const float*)d_in[16];

    const int* src = ei;
    const int* dst = ei + EE;

    float *xl, *xr, *h, *pea;
    int *deg, *part, *bsum, *off, *pos, *perm, *psrc;
    cudaGetSymbolAddress((void**)&xl,   g_xl);
    cudaGetSymbolAddress((void**)&xr,   g_xr);
    cudaGetSymbolAddress((void**)&h,    g_h);
    cudaGetSymbolAddress((void**)&deg,  g_deg);
    cudaGetSymbolAddress((void**)&part, g_part);
    cudaGetSymbolAddress((void**)&bsum, g_bsum);
    cudaGetSymbolAddress((void**)&off,  g_off);
    cudaGetSymbolAddress((void**)&pos,  g_pos);
    cudaGetSymbolAddress((void**)&perm, g_perm);
    cudaGetSymbolAddress((void**)&psrc, g_psrc);
    cudaGetSymbolAddress((void**)&pea,  g_pea);

    const int nodeTBlocks = (NN + TN - 1) / TN;          // 3125
    const int edgeTBlocks = (EE + 255) / 256;
    const int scanBlocks  = (NN + SCAN_B - 1) / SCAN_B;  // 391
    const int gatBlocks   = (NN * 2 + 7) / 8;            // warp per (node,head)

    // ---------- CSR build (by destination) + edge permutation ----------
    zero_deg_kernel<<<(NN + 255) / 256, 256>>>(deg);
    count_kernel<<<edgeTBlocks, 256>>>(dst, deg);
    scan1_kernel<<<scanBlocks, SCAN_B>>>(deg, part, bsum);
    scan2_kernel<<<1, 512>>>(bsum, scanBlocks);
    scan3_kernel<<<(NN + 255) / 256, 256>>>(part, bsum, off, pos);
    scatter_kernel<<<edgeTBlocks, 256>>>(dst, pos, perm);
    gather_edges_kernel<<<edgeTBlocks, 256>>>(perm, src, ea, psrc, pea);

    // ---------- layer 0: GATv2(79 -> 32, H=2, concat) -> width 64 ----------
    transform_kernel<<<nodeTBlocks, 64>>>(x, FNODE, 0, Wl0, bl0, Wr0, br0, 64, xl, xr);
    gat_node_kernel<64, 32, true><<<gatBlocks, 256>>>(xl, xr, psrc, off, pea, We0, att0, bias0, h);

    // ---------- layers 1,2: GATv2(64 -> 64, H=2, mean) ----------
    for (int L = 0; L < 2; L++) {
        const float* Wl   = Wl1   + (size_t)L * 64 * 128;
        const float* bl   = bl1   + (size_t)L * 128;
        const float* Wr   = Wr1   + (size_t)L * 64 * 128;
        const float* br   = br1   + (size_t)L * 128;
        const float* We   = We1   + (size_t)L * FEDGE * 128;
        const float* att  = att1  + (size_t)L * 2 * 64;
        const float* bias = bias1 + (size_t)L * 64;
        float* outp = (L == 1) ? (float*)d_out : h;

        transform_kernel<<<nodeTBlocks, 128>>>(h, 64, 1, Wl, bl, Wr, br, 128, xl, xr);
        gat_node_kernel<128, 64, false><<<gatBlocks, 256>>>(xl, xr, psrc, off, pea, We, att, bias, outp);
    }
}

// round 6
// speedup vs baseline: 1.1586x; 1.1586x over previous
#include <cuda_runtime.h>
#include <math.h>

#define NN 100000
#define EE 1600000
#define FNODE 79
#define FEDGE 10

// ---------------- scratch (device globals; no allocation) ----------------
__device__ float g_xl[NN * 128];
__device__ float g_xr[NN * 128];
__device__ float g_h[NN * 64];
__device__ int   g_deg[NN];
__device__ int   g_part[NN];
__device__ int   g_bsum[512];
__device__ int   g_off[NN + 1];
__device__ int   g_pos[NN];
__device__ int   g_perm[EE];
__device__ int   g_psrc[EE];
__device__ float g_pea[EE * 12];   // padded to 12 floats/edge for float4 loads

// ================= CSR build =================
__global__ void zero_deg_kernel(int* deg) {
    int i = blockIdx.x * blockDim.x + threadIdx.x;
    if (i < NN) deg[i] = 0;
}

__global__ void count_kernel(const int* __restrict__ dst, int* __restrict__ deg) {
    int e = blockIdx.x * blockDim.x + threadIdx.x;
    if (e < EE) atomicAdd(&deg[dst[e]], 1);
}

#define SCAN_B 256
__global__ void scan1_kernel(const int* __restrict__ deg, int* __restrict__ part,
                             int* __restrict__ bsum) {
    __shared__ int s[SCAN_B];
    int i = blockIdx.x * SCAN_B + threadIdx.x;
    int v = (i < NN) ? deg[i] : 0;
    s[threadIdx.x] = v;
    __syncthreads();
    for (int o = 1; o < SCAN_B; o <<= 1) {
        int t = (threadIdx.x >= o) ? s[threadIdx.x - o] : 0;
        __syncthreads();
        s[threadIdx.x] += t;
        __syncthreads();
    }
    if (i < NN) part[i] = s[threadIdx.x] - v;  // exclusive
    if (threadIdx.x == SCAN_B - 1) bsum[blockIdx.x] = s[threadIdx.x];
}

__global__ void scan2_kernel(int* __restrict__ bsum, int nb) {
    __shared__ int s[512];
    int t = threadIdx.x;
    int v = (t < nb) ? bsum[t] : 0;
    s[t] = v;
    __syncthreads();
    for (int o = 1; o < 512; o <<= 1) {
        int u = (t >= o) ? s[t - o] : 0;
        __syncthreads();
        s[t] += u;
        __syncthreads();
    }
    if (t < nb) bsum[t] = s[t] - v;  // exclusive
}

__global__ void scan3_kernel(const int* __restrict__ part, const int* __restrict__ bsum,
                             int* __restrict__ off, int* __restrict__ pos) {
    int i = blockIdx.x * blockDim.x + threadIdx.x;
    if (i < NN) {
        int o = part[i] + bsum[i / SCAN_B];
        off[i] = o;
        pos[i] = o;
    }
    if (i == 0) off[NN] = EE;
}

__global__ void scatter_kernel(const int* __restrict__ dst, int* __restrict__ pos,
                               int* __restrict__ perm) {
    int e = blockIdx.x * blockDim.x + threadIdx.x;
    if (e < EE) {
        int p = atomicAdd(&pos[dst[e]], 1);
        perm[p] = e;
    }
}

// permute src + edge_attr into CSR order (one-time; 12-float padded rows)
__global__ void gather_edges_kernel(const int* __restrict__ perm, const int* __restrict__ src,
                                    const float* __restrict__ ea,
                                    int* __restrict__ psrc, float* __restrict__ pea) {
    int j = blockIdx.x * blockDim.x + threadIdx.x;
    if (j >= EE) return;
    int e = perm[j];
    psrc[j] = src[e];
    const float* p = &ea[(size_t)e * FEDGE];
    float v[12];
#pragma unroll
    for (int k = 0; k < FEDGE; k++) v[k] = p[k];
    v[10] = 0.f; v[11] = 0.f;
    float4* o = (float4*)(pea + (size_t)j * 12);
    o[0] = make_float4(v[0], v[1], v[2], v[3]);
    o[1] = make_float4(v[4], v[5], v[6], v[7]);
    o[2] = make_float4(v[8], v[9], v[10], v[11]);
}

// ================= node transforms: xl = act(in)@Wl + bl ; xr likewise =================
#define TN 32
__global__ void transform_kernel(const float* __restrict__ in, int in_dim, int act,
                                 const float* __restrict__ Wl, const float* __restrict__ bl,
                                 const float* __restrict__ Wr, const float* __restrict__ br,
                                 int out_dim,
                                 float* __restrict__ xl, float* __restrict__ xr) {
    __shared__ float s_in[TN][FNODE + 1];
    int node0 = blockIdx.x * TN;
    int t = threadIdx.x;  // one output column per thread (blockDim.x == out_dim)

    int tot = TN * in_dim;
    for (int idx = t; idx < tot; idx += blockDim.x) {
        int n = idx / in_dim;
        int k = idx - n * in_dim;
        int g = node0 + n;
        float v = (g < NN) ? in[(size_t)g * in_dim + k] : 0.f;
        if (act) v = (v > 0.f) ? v : 0.01f * v;
        s_in[n][k] = v;
    }
    __syncthreads();

    float accl[TN], accr[TN];
    float blv = bl[t], brv = br[t];
#pragma unroll
    for (int n = 0; n < TN; n++) { accl[n] = blv; accr[n] = brv; }

    for (int k = 0; k < in_dim; k++) {
        float wl = Wl[k * out_dim + t];
        float wr = Wr[k * out_dim + t];
#pragma unroll
        for (int n = 0; n < TN; n++) {
            float v = s_in[n][k];
            accl[n] = fmaf(v, wl, accl[n]);
            accr[n] = fmaf(v, wr, accr[n]);
        }
    }
#pragma unroll
    for (int n = 0; n < TN; n++) {
        int g = node0 + n;
        if (g < NN) {
            xl[(size_t)g * out_dim + t] = accl[n];
            xr[(size_t)g * out_dim + t] = accr[n];
        }
    }
}

// ---------------- small vector load helpers ----------------
template <int NCH>
__device__ __forceinline__ void ldv(const float* __restrict__ p, float* d);
template <> __device__ __forceinline__ void ldv<2>(const float* __restrict__ p, float* d) {
    float2 v = *(const float2*)p; d[0] = v.x; d[1] = v.y;
}
template <> __device__ __forceinline__ void ldv<4>(const float* __restrict__ p, float* d) {
    float4 v = *(const float4*)p; d[0] = v.x; d[1] = v.y; d[2] = v.z; d[3] = v.w;
}

// ================= fused per-node GATv2 (vector-lane layout) =================
// one warp per destination node. Each lane owns NCH contiguous channels
// (channel base = lane*NCH). Head boundary at lane 16 -> 4-shfl butterfly
// reduces both heads' logits at once; each lane keeps its own head's softmax state.
template <int NCH, bool CONCAT>
__global__ void __launch_bounds__(256)
gat_node_kernel(const float* __restrict__ xl, const float* __restrict__ xr,
                const int* __restrict__ psrc, const int* __restrict__ off,
                const float* __restrict__ pea,
                const float* __restrict__ We, const float* __restrict__ att,
                const float* __restrict__ bias, float* __restrict__ out) {
    constexpr int HC = 32 * NCH;
    int t = threadIdx.x;
    int lane = t & 31;
    int n = blockIdx.x * 8 + (t >> 5);
    if (n >= NN) return;

    const int cb = lane * NCH;  // base channel for this lane

    // register-resident We, xr, att
    float Wv[FEDGE][NCH], xrv[NCH], attv[NCH];
#pragma unroll
    for (int k = 0; k < FEDGE; k++) ldv<NCH>(We + k * HC + cb, Wv[k]);
    ldv<NCH>(xr + (size_t)n * HC + cb, xrv);
    ldv<NCH>(att + cb, attv);

    float m = -INFINITY, dd = 0.f;
    float acc[NCH];
#pragma unroll
    for (int c = 0; c < NCH; c++) acc[c] = 0.f;

    int j0 = off[n], j1 = off[n + 1];
    int j = j0;
    for (; j + 1 < j1; j += 2) {
        int s0 = psrc[j], s1 = psrc[j + 1];
        const float4* e0 = (const float4*)(pea + (size_t)j * 12);
        const float4* e1 = (const float4*)(pea + (size_t)(j + 1) * 12);
        float4 A0 = e0[0], B0 = e0[1], C0 = e0[2];
        float4 A1 = e1[0], B1 = e1[1], C1 = e1[2];
        float a0[FEDGE] = {A0.x, A0.y, A0.z, A0.w, B0.x, B0.y, B0.z, B0.w, C0.x, C0.y};
        float a1[FEDGE] = {A1.x, A1.y, A1.z, A1.w, B1.x, B1.y, B1.z, B1.w, C1.x, C1.y};

        float xv0[NCH], xv1[NCH], z0[NCH], z1[NCH];
        ldv<NCH>(xl + (size_t)s0 * HC + cb, xv0);
        ldv<NCH>(xl + (size_t)s1 * HC + cb, xv1);
#pragma unroll
        for (int c = 0; c < NCH; c++) {
            z0[c] = xv0[c] + xrv[c];
            z1[c] = xv1[c] + xrv[c];
        }
#pragma unroll
        for (int k = 0; k < FEDGE; k++) {
#pragma unroll
            for (int c = 0; c < NCH; c++) {
                z0[c] = fmaf(a0[k], Wv[k][c], z0[c]);
                z1[c] = fmaf(a1[k], Wv[k][c], z1[c]);
            }
        }
        float p0 = 0.f, p1 = 0.f;
#pragma unroll
        for (int c = 0; c < NCH; c++) {
            float u = z0[c];
            u = (u > 0.f) ? u : 0.2f * u;
            p0 = fmaf(u, attv[c], p0);
            float v = z1[c];
            v = (v > 0.f) ? v : 0.2f * v;
            p1 = fmaf(v, attv[c], p1);
        }
        // dual-head butterfly: sums within each 16-lane half
#pragma unroll
        for (int o = 8; o > 0; o >>= 1) {
            p0 += __shfl_xor_sync(0xffffffffu, p0, o);
            p1 += __shfl_xor_sync(0xffffffffu, p1, o);
        }
        // online softmax (this lane's head)
        float nm = fmaxf(m, fmaxf(p0, p1));
        float cs = __expf(m - nm);
        float w0 = __expf(p0 - nm);
        float w1 = __expf(p1 - nm);
        dd = dd * cs + w0 + w1;
        m = nm;
#pragma unroll
        for (int c = 0; c < NCH; c++)
            acc[c] = fmaf(acc[c], cs, fmaf(w0, xv0[c], w1 * xv1[c]));
    }
    if (j < j1) {  // tail edge
        int s0 = psrc[j];
        const float4* e0 = (const float4*)(pea + (size_t)j * 12);
        float4 A0 = e0[0], B0 = e0[1], C0 = e0[2];
        float a0[FEDGE] = {A0.x, A0.y, A0.z, A0.w, B0.x, B0.y, B0.z, B0.w, C0.x, C0.y};
        float xv0[NCH], z0[NCH];
        ldv<NCH>(xl + (size_t)s0 * HC + cb, xv0);
#pragma unroll
        for (int c = 0; c < NCH; c++) z0[c] = xv0[c] + xrv[c];
#pragma unroll
        for (int k = 0; k < FEDGE; k++) {
#pragma unroll
            for (int c = 0; c < NCH; c++)
                z0[c] = fmaf(a0[k], Wv[k][c], z0[c]);
        }
        float p0 = 0.f;
#pragma unroll
        for (int c = 0; c < NCH; c++) {
            float u = z0[c];
            u = (u > 0.f) ? u : 0.2f * u;
            p0 = fmaf(u, attv[c], p0);
        }
#pragma unroll
        for (int o = 8; o > 0; o >>= 1)
            p0 += __shfl_xor_sync(0xffffffffu, p0, o);
        float nm = fmaxf(m, p0);
        float cs = __expf(m - nm);
        float w0 = __expf(p0 - nm);
        dd = dd * cs + w0;
        m = nm;
#pragma unroll
        for (int c = 0; c < NCH; c++)
            acc[c] = fmaf(acc[c], cs, w0 * xv0[c]);
    }

    float inv = 1.f / fmaxf(dd, 1e-16f);
    float y[NCH];
#pragma unroll
    for (int c = 0; c < NCH; c++) y[c] = acc[c] * inv;

    if (CONCAT) {
        // NCH==2: lane writes its 2 channels
        float2 o2 = make_float2(y[0] + bias[cb], y[1] + bias[cb + 1]);
        *(float2*)(out + (size_t)n * HC + cb) = o2;
    } else {
        // NCH==4: mean over heads. Lane i<16 holds head0 chans 4i..4i+3;
        // lane i+16 holds head1 chans 64+4i... -> exchange via xor 16.
        float z0_ = __shfl_xor_sync(0xffffffffu, y[0], 16);
        float z1_ = __shfl_xor_sync(0xffffffffu, y[1], 16);
        float z2_ = __shfl_xor_sync(0xffffffffu, y[2], 16);
        float z3_ = __shfl_xor_sync(0xffffffffu, y[3], 16);
        if (lane < 16) {
            int c = 4 * lane;
            float4 o4 = make_float4(0.5f * (y[0] + z0_) + bias[c],
                                    0.5f * (y[1] + z1_) + bias[c + 1],
                                    0.5f * (y[2] + z2_) + bias[c + 2],
                                    0.5f * (y[3] + z3_) + bias[c + 3]);
            *(float4*)(out + (size_t)n * 64 + c) = o4;
        }
    }
}

// ================= launch =================
extern "C" void kernel_launch(void* const* d_in, const int* in_sizes, int n_in,
                              void* d_out, int out_size) {
    const float* x    = (const float*)d_in[0];
    const int*   ei   = (const int*)d_in[1];
    const float* ea   = (const float*)d_in[2];
    const float* Wl0  = (const float*)d_in[3];
    const float* bl0  = (const float*)d_in[4];
    const float* Wr0  = (const float*)d_in[5];
    const float* br0  = (const float*)d_in[6];
    const float* We0  = (const float*)d_in[7];
    const float* att0 = (const float*)d_in[8];
    const float* bias0= (const float*)d_in[9];
    const float* Wl1  = (const float*)d_in[10];
    const float* bl1  = (const float*)d_in[11];
    const float* Wr1  = (const float*)d_in[12];
    const float* br1  = (const float*)d_in[13];
    const float* We1  = (const float*)d_in[14];
    const float* att1 = (const float*)d_in[15];
    const float* bias1= (const float*)d_in[16];

    const int* src = ei;
    const int* dst = ei + EE;

    float *xl, *xr, *h, *pea;
    int *deg, *part, *bsum, *off, *pos, *perm, *psrc;
    cudaGetSymbolAddress((void**)&xl,   g_xl);
    cudaGetSymbolAddress((void**)&xr,   g_xr);
    cudaGetSymbolAddress((void**)&h,    g_h);
    cudaGetSymbolAddress((void**)&deg,  g_deg);
    cudaGetSymbolAddress((void**)&part, g_part);
    cudaGetSymbolAddress((void**)&bsum, g_bsum);
    cudaGetSymbolAddress((void**)&off,  g_off);
    cudaGetSymbolAddress((void**)&pos,  g_pos);
    cudaGetSymbolAddress((void**)&perm, g_perm);
    cudaGetSymbolAddress((void**)&psrc, g_psrc);
    cudaGetSymbolAddress((void**)&pea,  g_pea);

    const int nodeTBlocks = (NN + TN - 1) / TN;          // 3125
    const int edgeTBlocks = (EE + 255) / 256;
    const int scanBlocks  = (NN + SCAN_B - 1) / SCAN_B;  // 391
    const int gatBlocks   = (NN + 7) / 8;                // warp per node

    // ---------- CSR build (by destination) + edge permutation ----------
    zero_deg_kernel<<<(NN + 255) / 256, 256>>>(deg);
    count_kernel<<<edgeTBlocks, 256>>>(dst, deg);
    scan1_kernel<<<scanBlocks, SCAN_B>>>(deg, part, bsum);
    scan2_kernel<<<1, 512>>>(bsum, scanBlocks);
    scan3_kernel<<<(NN + 255) / 256, 256>>>(part, bsum, off, pos);
    scatter_kernel<<<edgeTBlocks, 256>>>(dst, pos, perm);
    gather_edges_kernel<<<edgeTBlocks, 256>>>(perm, src, ea, psrc, pea);

    // ---------- layer 0: GATv2(79 -> 32, H=2, concat) -> width 64 ----------
    transform_kernel<<<nodeTBlocks, 64>>>(x, FNODE, 0, Wl0, bl0, Wr0, br0, 64, xl, xr);
    gat_node_kernel<2, true><<<gatBlocks, 256>>>(xl, xr, psrc, off, pea, We0, att0, bias0, h);

    // ---------- layers 1,2: GATv2(64 -> 64, H=2, mean) ----------
    for (int L = 0; L < 2; L++) {
        const float* Wl   = Wl1   + (size_t)L * 64 * 128;
        const float* bl   = bl1   + (size_t)L * 128;
        const float* Wr   = Wr1   + (size_t)L * 64 * 128;
        const float* br   = br1   + (size_t)L * 128;
        const float* We   = We1   + (size_t)L * FEDGE * 128;
        const float* att  = att1  + (size_t)L * 2 * 64;
        const float* bias = bias1 + (size_t)L * 64;
        float* outp = (L == 1) ? (float*)d_out : h;

        transform_kernel<<<nodeTBlocks, 128>>>(h, 64, 1, Wl, bl, Wr, br, 128, xl, xr);
        gat_node_kernel<4, false><<<gatBlocks, 256>>>(xl, xr, psrc, off, pea, We, att, bias, outp);
    }
}